// round 4
// baseline (speedup 1.0000x reference)
#include <cuda_runtime.h>
#include <math.h>

#define NB 64
#define NT 512
#define NE 256
#define NH 512

typedef unsigned long long u64;

// ---------------- device scratch (static, no runtime allocation) ----------------
__device__ __align__(256) float g_xe[2][NT][NB][NH];   // input projections [branch][t][b][h] (128 MB)
__device__ __align__(256) float g_h[2][2][NB][NH];     // double-buffered hidden state per branch

// ---------------- small helpers ----------------
__device__ __forceinline__ void unpack2(u64 v, float& lo, float& hi) {
    asm("mov.b64 {%0, %1}, %2;" : "=f"(lo), "=f"(hi) : "l"(v));
}
__device__ __forceinline__ void fma2(u64& d, u64 a, u64 b) {
    asm("fma.rn.f32x2 %0, %1, %2, %3;" : "=l"(d) : "l"(a), "l"(b), "l"(d));
}
__device__ __forceinline__ float tanh_fast(float x) {
    float y; asm("tanh.approx.f32 %0, %1;" : "=f"(y) : "f"(x)); return y;
}
__device__ __forceinline__ void cp16cg(void* smem_dst, const void* gsrc) {
    unsigned sd = (unsigned)__cvta_generic_to_shared(smem_dst);
    asm volatile("cp.async.cg.shared.global [%0], [%1], 16;" :: "r"(sd), "l"(gsrc));
}
#define CP_COMMIT() asm volatile("cp.async.commit_group;" ::: "memory")
#define CP_WAIT0()  asm volatile("cp.async.wait_group 0;" ::: "memory")
#define CLUSTER_ARRIVE() asm volatile("barrier.cluster.arrive.aligned;" ::: "memory")
#define CLUSTER_WAIT()   asm volatile("barrier.cluster.wait.aligned;"   ::: "memory")

// ---------------- out init: out[b] = fc_b ----------------
__global__ void init_out_kernel(float* out, const float* __restrict__ fcb) {
    if (threadIdx.x < NB) out[threadIdx.x] = fcb[0];
}

// ---------------- projection: xe[br][t][b][:] = emb_table[x[b,t]] @ Wx + bias ----------------
// K-paired f32x2 GEMM: A_s [m][k], B_s transposed [n][k]; thread tile 4r x 4c.
__global__ __launch_bounds__(256) void proj_kernel(
    const int* __restrict__ x, const float* __restrict__ emb,
    const float* __restrict__ Wx0, const float* __restrict__ b0,
    const float* __restrict__ Wx1, const float* __restrict__ b1)
{
    __shared__ float A_s[64][68];   // [m][k] padded (272B rows, 16B aligned)
    __shared__ float B_s[64][68];   // [n][k] transposed, padded
    __shared__ int   xrow[64];

    const int tid = threadIdx.x;
    const int n0  = blockIdx.x * 64;
    const int my  = blockIdx.y;
    const int br  = blockIdx.z;
    const int b   = my >> 3;
    const int t0  = (my & 7) << 6;

    const float* Wx   = br ? Wx1 : Wx0;
    const float* bias = br ? b1  : b0;

    if (tid < 64) xrow[tid] = x[b * NT + t0 + tid];
    __syncthreads();

    const int mg = tid >> 4;   // 16 groups x 4 rows
    const int ni = tid & 15;   // 16 groups x 4 cols

    u64 acc[4][4];
#pragma unroll
    for (int i = 0; i < 4; i++)
#pragma unroll
        for (int j = 0; j < 4; j++) acc[i][j] = 0ULL;

    for (int kt = 0; kt < 4; kt++) {
        // stage A (gathered embedding rows), [m][k]
        for (int l = tid; l < 1024; l += 256) {
            int r = l >> 4, jj = l & 15;
            float4 v = *(const float4*)(emb + (size_t)xrow[r] * NE + kt * 64 + jj * 4);
            *(float4*)&A_s[r][jj * 4] = v;
        }
        // stage B transposed: B_s[n][k] <- Wx[k][n]
        for (int l = tid; l < 1024; l += 256) {
            int kk = l >> 4, jj = l & 15;
            float4 v = *(const float4*)(Wx + (size_t)(kt * 64 + kk) * NH + n0 + jj * 4);
            B_s[jj * 4 + 0][kk] = v.x;
            B_s[jj * 4 + 1][kk] = v.y;
            B_s[jj * 4 + 2][kk] = v.z;
            B_s[jj * 4 + 3][kk] = v.w;
        }
        __syncthreads();

#pragma unroll
        for (int k4 = 0; k4 < 16; k4++) {
            ulonglong2 av[4], bv[4];
#pragma unroll
            for (int i = 0; i < 4; i++)
                av[i] = *(const ulonglong2*)&A_s[mg * 4 + i][k4 * 4];
#pragma unroll
            for (int j = 0; j < 4; j++)
                bv[j] = *(const ulonglong2*)&B_s[ni * 4 + j][k4 * 4];
#pragma unroll
            for (int i = 0; i < 4; i++)
#pragma unroll
                for (int j = 0; j < 4; j++) {
                    fma2(acc[i][j], av[i].x, bv[j].x);
                    fma2(acc[i][j], av[i].y, bv[j].y);
                }
        }
        __syncthreads();
    }

    float4 bb = *(const float4*)(bias + n0 + ni * 4);
    const float bbv[4] = {bb.x, bb.y, bb.z, bb.w};
#pragma unroll
    for (int i = 0; i < 4; i++) {
        int t = t0 + mg * 4 + i;
        float o[4];
#pragma unroll
        for (int j = 0; j < 4; j++) {
            float lo, hi; unpack2(acc[i][j], lo, hi);
            o[j] = lo + hi + bbv[j];
        }
        *(float4*)&g_xe[br][t][b][n0 + ni * 4] = make_float4(o[0], o[1], o[2], o[3]);
    }
}

// ---------------- persistent recurrence ----------------
// 128 CTAs x 256 threads, clusters of 8 (one bg row). Per branch: 8 bg (8 rows) x 8 cg
// (64 cols). CTA keeps Wh[:, 64 cols] column-major in SMEM (padded stride 516) for all
// 512 steps. Per step: 4 cp.async/thread stage the 8 h rows (padded rows, conflict-free),
// inner product is K-paired f32x2 straight from LDS.128 (no packs, no dups).
#define WPAD 516
extern __shared__ float rec_smem[];
__global__ __launch_bounds__(256, 1) __cluster_dims__(8, 1, 1)
void rec_kernel(const float* __restrict__ Wh0, const float* __restrict__ Wh1,
                const float* __restrict__ fcw, float* out)
{
    float* W_s = rec_smem;                 // [64 cols][516]  (132 KB)
    float* h_s = rec_smem + 64 * WPAD;     // [8 rows][516]   (16.5 KB)

    const int tid = threadIdx.x;
    const int bx  = blockIdx.x;
    const int br  = bx >> 6;
    const int id  = bx & 63;
    const int bg  = id >> 3;
    const int cg  = id & 7;
    const int c0  = cg * 64;
    const float* Wh = br ? Wh1 : Wh0;

    // transpose-load persistent W slice: W_s[c][k] <- Wh[k][c0+c]
    for (int l = tid; l < NH * 16; l += 256) {
        int k = l >> 4, q = l & 15;
        float4 v = *(const float4*)&Wh[(size_t)k * NH + c0 + q * 4];
        W_s[(q * 4 + 0) * WPAD + k] = v.x;
        W_s[(q * 4 + 1) * WPAD + k] = v.y;
        W_s[(q * 4 + 2) * WPAD + k] = v.z;
        W_s[(q * 4 + 3) * WPAD + k] = v.w;
    }

    const int lane = tid & 31;
    const int wid  = tid >> 5;
    const int r    = lane >> 2;            // 0..7 row within bg
    const int cp   = lane & 3;             // col pair
    const int b    = bg * 8 + r;
    const int cl   = wid * 8 + cp * 2;     // local col (0..63)
    const int c    = c0 + cl;

    // zero h parity-0 slice (re-done every launch => replay-deterministic)
    __stcg((float2*)&g_h[br][0][b][c], make_float2(0.f, 0.f));

    __syncthreads();
    CLUSTER_ARRIVE(); CLUSTER_WAIT();      // W_s + zeroed h visible

    const ulonglong2* wp0 = (const ulonglong2*)(W_s + (size_t)cl * WPAD);
    const ulonglong2* wp1 = (const ulonglong2*)(W_s + (size_t)(cl + 1) * WPAD);
    const ulonglong2* hp  = (const ulonglong2*)(h_s + (size_t)r * WPAD);

    float v0 = 0.f, v1 = 0.f;

    for (int t = 0; t < NT; t++) {
        // stage h(t): warp wid stages row wid (2 KB), 4 x 16B per thread
        {
            const float* src = &g_h[br][t & 1][bg * 8 + wid][0];
            float* dst = h_s + wid * WPAD;
#pragma unroll
            for (int i = 0; i < 4; i++) {
                int q = (lane + i * 32) * 4;
                cp16cg(dst + q, src + q);
            }
        }
        CP_COMMIT();
        float2 xe2 = __ldcg((const float2*)&g_xe[br][t][b][c]);
        CP_WAIT0();
        __syncthreads();

        u64 a0 = 0ULL, a1 = 0ULL, a2 = 0ULL, a3 = 0ULL;
#pragma unroll 8
        for (int k4 = 0; k4 < NH / 4; k4++) {
            ulonglong2 hv = hp[k4];
            ulonglong2 w0 = wp0[k4];
            ulonglong2 w1 = wp1[k4];
            fma2(a0, hv.x, w0.x);
            fma2(a1, hv.y, w0.y);
            fma2(a2, hv.x, w1.x);
            fma2(a3, hv.y, w1.y);
        }

        float x0, x1, x2, x3, y0, y1, y2, y3;
        unpack2(a0, x0, x1); unpack2(a1, x2, x3);
        unpack2(a2, y0, y1); unpack2(a3, y2, y3);
        float s0 = (x0 + x1) + (x2 + x3) + xe2.x;
        float s1 = (y0 + y1) + (y2 + y3) + xe2.y;
        if (br) { v0 = fmaxf(s0, 0.f); v1 = fmaxf(s1, 0.f); }
        else    { v0 = tanh_fast(s0);  v1 = tanh_fast(s1);  }

        __stcg((float2*)&g_h[br][(t + 1) & 1][b][c], make_float2(v0, v1));

        CLUSTER_ARRIVE();                   // release h writes cluster-wide
        CLUSTER_WAIT();                     // acquire peers' writes
    }

    // out[b] += v0*fcw[c] + v1*fcw[c+1], reduced over cp lanes then atomics
    const float f0 = fcw[br * NH + c];
    const float f1 = fcw[br * NH + c + 1];
    float p = v0 * f0 + v1 * f1;
    p += __shfl_down_sync(0xffffffffu, p, 2, 4);
    p += __shfl_down_sync(0xffffffffu, p, 1, 4);
    if (cp == 0) atomicAdd(&out[b], p);
}

// ---------------- launch ----------------
extern "C" void kernel_launch(void* const* d_in, const int* in_sizes, int n_in,
                              void* d_out, int out_size) {
    const int*   x    = (const int*)  d_in[0];
    const float* emb  = (const float*)d_in[1];
    const float* Wx0  = (const float*)d_in[2];
    const float* Wh0  = (const float*)d_in[3];
    const float* b0   = (const float*)d_in[4];
    const float* Wx1  = (const float*)d_in[5];
    const float* Wh1  = (const float*)d_in[6];
    const float* b1   = (const float*)d_in[7];
    const float* fcw  = (const float*)d_in[8];
    const float* fcb  = (const float*)d_in[9];
    float* out = (float*)d_out;

    const int rec_smem_bytes = (64 * WPAD + 8 * WPAD) * (int)sizeof(float);
    cudaFuncSetAttribute(rec_kernel, cudaFuncAttributeMaxDynamicSharedMemorySize,
                         rec_smem_bytes);

    init_out_kernel<<<1, 64>>>(out, fcb);
    proj_kernel<<<dim3(8, 512, 2), 256>>>(x, emb, Wx0, b0, Wx1, b1);
    rec_kernel<<<128, 256, rec_smem_bytes>>>(Wh0, Wh1, fcw, out);
}

// round 5
// speedup vs baseline: 1.0450x; 1.0450x over previous
#include <cuda_runtime.h>
#include <math.h>

#define NB 64
#define NT 512
#define NE 256
#define NH 512
#define WPAD 516

typedef unsigned long long u64;

// ---------------- device scratch (static, no runtime allocation) ----------------
__device__ __align__(256) float g_xe[2][NT][NB][NH];   // input projections [branch][t][b][h] (128 MB)

// ---------------- small helpers ----------------
__device__ __forceinline__ void unpack2(u64 v, float& lo, float& hi) {
    asm("mov.b64 {%0, %1}, %2;" : "=f"(lo), "=f"(hi) : "l"(v));
}
__device__ __forceinline__ u64 pack2(float lo, float hi) {
    u64 r; asm("mov.b64 %0, {%1, %2};" : "=l"(r) : "f"(lo), "f"(hi)); return r;
}
__device__ __forceinline__ void fma2(u64& d, u64 a, u64 b) {
    asm("fma.rn.f32x2 %0, %1, %2, %3;" : "=l"(d) : "l"(a), "l"(b), "l"(d));
}
__device__ __forceinline__ float tanh_fast(float x) {
    float y; asm("tanh.approx.f32 %0, %1;" : "=f"(y) : "f"(x)); return y;
}
__device__ __forceinline__ unsigned smem_u32(const void* p) {
    return (unsigned)__cvta_generic_to_shared(p);
}
__device__ __forceinline__ unsigned mapa_u32(unsigned laddr, unsigned rank) {
    unsigned d;
    asm("mapa.shared::cluster.u32 %0, %1, %2;" : "=r"(d) : "r"(laddr), "r"(rank));
    return d;
}
__device__ __forceinline__ void st_cluster64(unsigned raddr, u64 v) {
    asm volatile("st.shared::cluster.b64 [%0], %1;" :: "r"(raddr), "l"(v) : "memory");
}
#define CLUSTER_SYNC() do { \
    asm volatile("barrier.cluster.arrive.aligned;" ::: "memory"); \
    asm volatile("barrier.cluster.wait.aligned;"   ::: "memory"); \
} while (0)

// ---------------- projection: xe[br][t][b][:] = emb_table[x[b,t]] @ Wx + bias ----------------
// K-paired f32x2 GEMM: A_s [m][k], B_s transposed [n][k]; thread tile 4r x 4c.
// Also initializes out[b] = fc_b (block 0 only) so no separate init kernel.
__global__ __launch_bounds__(256) void proj_kernel(
    const int* __restrict__ x, const float* __restrict__ emb,
    const float* __restrict__ Wx0, const float* __restrict__ b0,
    const float* __restrict__ Wx1, const float* __restrict__ b1,
    const float* __restrict__ fcb, float* out)
{
    __shared__ float A_s[64][68];
    __shared__ float B_s[64][68];
    __shared__ int   xrow[64];

    const int tid = threadIdx.x;
    const int n0  = blockIdx.x * 64;
    const int my  = blockIdx.y;
    const int br  = blockIdx.z;
    const int b   = my >> 3;
    const int t0  = (my & 7) << 6;

    if (blockIdx.x == 0 && blockIdx.y == 0 && blockIdx.z == 0 && tid < NB)
        out[tid] = fcb[0];

    const float* Wx   = br ? Wx1 : Wx0;
    const float* bias = br ? b1  : b0;

    if (tid < 64) xrow[tid] = x[b * NT + t0 + tid];
    __syncthreads();

    const int mg = tid >> 4;
    const int ni = tid & 15;

    u64 acc[4][4];
#pragma unroll
    for (int i = 0; i < 4; i++)
#pragma unroll
        for (int j = 0; j < 4; j++) acc[i][j] = 0ULL;

    for (int kt = 0; kt < 4; kt++) {
        for (int l = tid; l < 1024; l += 256) {
            int r = l >> 4, jj = l & 15;
            float4 v = *(const float4*)(emb + (size_t)xrow[r] * NE + kt * 64 + jj * 4);
            *(float4*)&A_s[r][jj * 4] = v;
        }
        for (int l = tid; l < 1024; l += 256) {
            int kk = l >> 4, jj = l & 15;
            float4 v = *(const float4*)(Wx + (size_t)(kt * 64 + kk) * NH + n0 + jj * 4);
            B_s[jj * 4 + 0][kk] = v.x;
            B_s[jj * 4 + 1][kk] = v.y;
            B_s[jj * 4 + 2][kk] = v.z;
            B_s[jj * 4 + 3][kk] = v.w;
        }
        __syncthreads();

#pragma unroll
        for (int k4 = 0; k4 < 16; k4++) {
            ulonglong2 av[4], bv[4];
#pragma unroll
            for (int i = 0; i < 4; i++)
                av[i] = *(const ulonglong2*)&A_s[mg * 4 + i][k4 * 4];
#pragma unroll
            for (int j = 0; j < 4; j++)
                bv[j] = *(const ulonglong2*)&B_s[ni * 4 + j][k4 * 4];
#pragma unroll
            for (int i = 0; i < 4; i++)
#pragma unroll
                for (int j = 0; j < 4; j++) {
                    fma2(acc[i][j], av[i].x, bv[j].x);
                    fma2(acc[i][j], av[i].y, bv[j].y);
                }
        }
        __syncthreads();
    }

    float4 bb = *(const float4*)(bias + n0 + ni * 4);
    const float bbv[4] = {bb.x, bb.y, bb.z, bb.w};
#pragma unroll
    for (int i = 0; i < 4; i++) {
        int t = t0 + mg * 4 + i;
        float o[4];
#pragma unroll
        for (int j = 0; j < 4; j++) {
            float lo, hi; unpack2(acc[i][j], lo, hi);
            o[j] = lo + hi + bbv[j];
        }
        *(float4*)&g_xe[br][t][b][n0 + ni * 4] = make_float4(o[0], o[1], o[2], o[3]);
    }
}

// ---------------- persistent recurrence (DSMEM exchange, no global h) ----------------
// 128 CTAs x 256 threads, clusters of 8 = one batch-group (8 rows). Per branch:
// 8 bg x 8 cg (64 cols each). CTA keeps Wh[:, 64 cols] column-major in SMEM (132 KB)
// plus a double-buffered full-width h copy for its 8 rows (2 x 8 x 512, 33 KB).
// Per step: k-loop reads LOCAL smem only; results pushed to all 8 peers' next-step
// buffer via st.shared::cluster (addresses precomputed); one barrier.cluster per step
// (arrive=release / wait=acquire orders the DSMEM stores).
extern __shared__ float rec_smem[];
__global__ __launch_bounds__(256, 1) __cluster_dims__(8, 1, 1)
void rec_kernel(const float* __restrict__ Wh0, const float* __restrict__ Wh1,
                const float* __restrict__ fcw, float* out)
{
    float* W_s = rec_smem;                 // [64 cols][WPAD]
    float* h_s = rec_smem + 64 * WPAD;     // [2 bufs][8 rows][WPAD]

    const int tid = threadIdx.x;
    const int bx  = blockIdx.x;
    const int br  = bx >> 6;
    const int id  = bx & 63;
    const int bg  = id >> 3;
    const int cg  = id & 7;                // == cluster rank (consecutive blockIdx)
    const int c0  = cg * 64;
    const float* Wh = br ? Wh1 : Wh0;

    // transpose-load persistent W slice: W_s[c][k] <- Wh[k][c0+c]
    for (int l = tid; l < NH * 16; l += 256) {
        int k = l >> 4, q = l & 15;
        float4 v = *(const float4*)&Wh[(size_t)k * NH + c0 + q * 4];
        W_s[(q * 4 + 0) * WPAD + k] = v.x;
        W_s[(q * 4 + 1) * WPAD + k] = v.y;
        W_s[(q * 4 + 2) * WPAD + k] = v.z;
        W_s[(q * 4 + 3) * WPAD + k] = v.w;
    }
    // zero local h buffer 0 (full 512 cols x 8 rows)
    for (int l = tid; l < 8 * NH; l += 256)
        h_s[(l >> 9) * WPAD + (l & 511)] = 0.f;

    const int lane = tid & 31;
    const int wid  = tid >> 5;
    const int r    = lane >> 2;            // 0..7 local batch row
    const int cp   = lane & 3;
    const int b    = bg * 8 + r;
    const int cl   = wid * 8 + cp * 2;     // local col pair base (0..62, even)
    const int c    = c0 + cl;              // global col

    // precompute remote store addresses into both buffers for all 8 ranks
    unsigned la0 = smem_u32(&h_s[0 * 8 * WPAD + r * WPAD + c]);
    unsigned la1 = smem_u32(&h_s[1 * 8 * WPAD + r * WPAD + c]);
    unsigned ra0[8], ra1[8];
#pragma unroll
    for (int p = 0; p < 8; p++) {
        ra0[p] = mapa_u32(la0, p);
        ra1[p] = mapa_u32(la1, p);
    }

    __syncthreads();
    CLUSTER_SYNC();                         // W_s + zeroed buf0 ready cluster-wide

    const ulonglong2* wp0 = (const ulonglong2*)(W_s + (size_t)cl * WPAD);
    const ulonglong2* wp1 = (const ulonglong2*)(W_s + (size_t)(cl + 1) * WPAD);

    float v0 = 0.f, v1 = 0.f;

    for (int t = 0; t < NT; t++) {
        // xe prefetch (independent of h; overlaps the k-loop)
        float2 xe2 = __ldcs((const float2*)&g_xe[br][t][b][c]);

        const ulonglong2* hp =
            (const ulonglong2*)(h_s + (size_t)(t & 1) * 8 * WPAD + (size_t)r * WPAD);

        u64 a0 = 0ULL, a1 = 0ULL, a2 = 0ULL, a3 = 0ULL;
#pragma unroll 8
        for (int k4 = 0; k4 < NH / 4; k4++) {
            ulonglong2 hv = hp[k4];
            ulonglong2 w0 = wp0[k4];
            ulonglong2 w1 = wp1[k4];
            fma2(a0, hv.x, w0.x);
            fma2(a1, hv.y, w0.y);
            fma2(a2, hv.x, w1.x);
            fma2(a3, hv.y, w1.y);
        }

        float x0, x1, x2, x3, y0, y1, y2, y3;
        unpack2(a0, x0, x1); unpack2(a1, x2, x3);
        unpack2(a2, y0, y1); unpack2(a3, y2, y3);
        float s0 = (x0 + x1) + (x2 + x3) + xe2.x;
        float s1 = (y0 + y1) + (y2 + y3) + xe2.y;
        if (br) { v0 = fmaxf(s0, 0.f); v1 = fmaxf(s1, 0.f); }
        else    { v0 = tanh_fast(s0);  v1 = tanh_fast(s1);  }

        // push result pair into every peer's next-step buffer
        u64 val = pack2(v0, v1);
        const unsigned* ra = (t & 1) ? ra0 : ra1;   // next buf = (t+1)&1
#pragma unroll
        for (int p = 0; p < 8; p++) st_cluster64(ra[p], val);

        CLUSTER_SYNC();   // release our stores / acquire peers' stores
    }

    // out[b] += v0*fcw[c] + v1*fcw[c+1]; reduce across cp lanes, then atomics
    const float f0 = fcw[br * NH + c];
    const float f1 = fcw[br * NH + c + 1];
    float p = v0 * f0 + v1 * f1;
    p += __shfl_down_sync(0xffffffffu, p, 2, 4);
    p += __shfl_down_sync(0xffffffffu, p, 1, 4);
    if (cp == 0) atomicAdd(&out[b], p);
    // last in-loop CLUSTER_SYNC already fenced the final DSMEM stores; safe to exit
}

// ---------------- launch ----------------
extern "C" void kernel_launch(void* const* d_in, const int* in_sizes, int n_in,
                              void* d_out, int out_size) {
    const int*   x    = (const int*)  d_in[0];
    const float* emb  = (const float*)d_in[1];
    const float* Wx0  = (const float*)d_in[2];
    const float* Wh0  = (const float*)d_in[3];
    const float* b0   = (const float*)d_in[4];
    const float* Wx1  = (const float*)d_in[5];
    const float* Wh1  = (const float*)d_in[6];
    const float* b1   = (const float*)d_in[7];
    const float* fcw  = (const float*)d_in[8];
    const float* fcb  = (const float*)d_in[9];
    float* out = (float*)d_out;

    const int rec_smem_bytes = (64 * WPAD + 2 * 8 * WPAD) * (int)sizeof(float);
    cudaFuncSetAttribute(rec_kernel, cudaFuncAttributeMaxDynamicSharedMemorySize,
                         rec_smem_bytes);

    proj_kernel<<<dim3(8, 512, 2), 256>>>(x, emb, Wx0, b0, Wx1, b1, fcb, out);
    rec_kernel<<<128, 256, rec_smem_bytes>>>(Wh0, Wh1, fcw, out);
}